// round 15
// baseline (speedup 1.0000x reference)
#include <cuda_runtime.h>
#include <cuda_fp16.h>
#include <cuda_bf16.h>
#include <math.h>

#define BB 4
#define CC 64
#define OO 64
#define HH 128
#define WW 128
#define CHS (HH * WW)
#define NC4 (CC / 4)

// SMEM float offsets (per CTA): union {exsh 28x132=3696 | vsh 2x4x9x128=9216}
#define UNI_F 0
#define BN_F  9216
#define SMEM_FLOATS (BN_F + 128)     // 9344 floats = 37,376 B

typedef unsigned long long ull;

// channel-packed fp16 image: g_x4[b][c4][y][x] = 4 halves (ch 4c4..4c4+3)
__device__ ull g_x4[(size_t)BB * NC4 * CHS];
// reordered main weights: g_wr[ck][64], o-interleaved (o=og*8+ch*4+ri -> ch*32+og*4+ri)
__device__ float g_wr[576 * 64];
// reordered offset weights: g_wor[ck][32] (half0: oc0..13 @0..13, half1: oc14..26 @16..28, rest 0)
__device__ float g_wor[576 * 32];

__device__ __forceinline__ ull pack2(float lo, float hi) {
    ull r; asm("mov.b64 %0, {%1, %2};" : "=l"(r) : "f"(lo), "f"(hi)); return r;
}
__device__ __forceinline__ void unpack2(ull v, float& lo, float& hi) {
    asm("mov.b64 {%0, %1}, %2;" : "=f"(lo), "=f"(hi) : "l"(v));
}
__device__ __forceinline__ ull ffma2(ull a, ull b, ull c) {
    ull d; asm("fma.rn.f32x2 %0, %1, %2, %3;" : "=l"(d) : "l"(a), "l"(b), "l"(c)); return d;
}

#define BAR_SYNC(id)   asm volatile("bar.sync %0, 256;"   :: "r"(id) : "memory")
#define BAR_ARRIVE(id) asm volatile("bar.arrive %0, 256;" :: "r"(id) : "memory")
#define PBAR_SYNC()    asm volatile("bar.sync 9, 128;" ::: "memory")

// ---------------------------------------------------------------------------
// Pre-pass 1: pack 4 channels per pixel into one ull of fp16.
// ---------------------------------------------------------------------------
__global__ void __launch_bounds__(256) pack4_kernel(const float* __restrict__ x)
{
    int i = blockIdx.x * 256 + threadIdx.x;          // 0 .. BB*NC4*CHS-1
    int pix = i & (CHS - 1);
    int c4  = (i >> 14) & (NC4 - 1);
    int b   = i >> 18;
    const float* xp = x + ((size_t)(b * CC + c4 * 4) << 14) + pix;
    __half2 lo = __floats2half2_rn(xp[0],       xp[CHS]);
    __half2 hi = __floats2half2_rn(xp[2 * CHS], xp[3 * CHS]);
    unsigned ulo = *reinterpret_cast<unsigned*>(&lo);
    unsigned uhi = *reinterpret_cast<unsigned*>(&hi);
    g_x4[i] = ((ull)uhi << 32) | ulo;
}

// ---------------------------------------------------------------------------
// Pre-pass 2: reorder weights into GEMM-friendly global layouts.
// ---------------------------------------------------------------------------
__global__ void __launch_bounds__(256) reorder_kernel(
    const float* __restrict__ weight, const float* __restrict__ w_off)
{
    int i = blockIdx.x * 256 + threadIdx.x;
    if (i < 64 * 576) {
        int o = i / 576, ck = i % 576;
        int og = o >> 3, r = o & 7, ch = r >> 2, ri = r & 3;
        g_wr[ck * 64 + ch * 32 + og * 4 + ri] = weight[i];
    } else if (i < 64 * 576 + 576 * 32) {
        int j  = i - 64 * 576;
        int ck = j >> 5, sl = j & 31;
        int hf = sl >> 4, jj = sl & 15;
        int oc = hf * 14 + jj;
        float v = (jj < 14 && oc < 27) ? w_off[oc * 576 + ck] : 0.0f;
        g_wor[ck * 32 + sl] = v;
    }
}

// ---------------------------------------------------------------------------
// Fused DCNv2 + BN + ReLU. CTA = 1 row (128 px), 256 threads, 2 CTAs/SM.
// Phase 1 (offset conv, fp32 x, weights via uniform __ldg): all 8 warps.
// Phase 2: warps 0-3 = samplers (g_x4 gathers -> ring), warps 4-7 =
// consumers (FFMA2 GEMM, weights via uniform __ldg). Ring: 2 slots x 4 ch.
// ---------------------------------------------------------------------------
__global__ void __launch_bounds__(256, 2) dcn_2c_kernel(
    const float* __restrict__ x,
    const float* __restrict__ b_off,
    const float* __restrict__ bias,
    const float* __restrict__ gamma,
    const float* __restrict__ beta,
    const float* __restrict__ rmean,
    const float* __restrict__ rvar,
    float* __restrict__ out)
{
    extern __shared__ float sm[];
    float* exsh   = sm + UNI_F;    // [28][132]   (offset exchange)
    float* vsh    = sm + UNI_F;    // [2 slots][4 ch][9][128] (phase 2 ring)
    float* bscale = sm + BN_F;
    float* bshift = bscale + 64;

    const int tid  = threadIdx.x;
    const int lane = tid & 31;
    const int w2   = tid >> 5;

    if (tid < 64) {
        int o = tid;
        float sc = gamma[o] * rsqrtf(rvar[o] + 1e-5f);
        bscale[o] = sc;
        bshift[o] = (bias[o] - rmean[o]) * sc + beta[o];
    }

    const int gr = blockIdx.x;       // global row 0..511
    const int b  = gr >> 7;
    const int h  = gr & 127;
    const float* xb = x + (size_t)b * CC * CHS;
    const ull* x4b  = g_x4 + (size_t)b * NC4 * CHS;

    // =======================================================================
    // Phase 1: offset conv (all 256 threads; lane-pair split; fp32 x,
    // uniform __ldg weights)
    // =======================================================================
    {
        const int p     = w2 * 16 + (lane & 15);   // pixel 0..127
        const int halfp = lane >> 4;

        const int ty0[5] = {-1, -1, -1, 0, 0}, tx0[5] = {-1, 0, 1, -1, 0};
        const int ty1[5] = {0, 0, 1, 1, 1},    tx1[5] = {0, 1, -1, 0, 1};
        int p1o[5]; bool p1v[5];
#pragma unroll
        for (int j = 0; j < 5; j++) {
            int ty = halfp ? ty1[j] : ty0[j];
            int tx = halfp ? tx1[j] : tx0[j];
            int y = h + ty, xx = p + tx;
            p1v[j] = (y >= 0) & (y < HH) & (xx >= 0) & (xx < WW);
            p1o[j] = y * WW + xx;
        }
        int kord[9];
#pragma unroll
        for (int i = 0; i < 9; i++) kord[i] = halfp ? (4 + i) % 9 : i;

        ull offa[7];
        {
            int chb = halfp * 14;
#pragma unroll
            for (int j = 0; j < 7; j++) {
                int i1 = chb + 2 * j + 1;
                float lo = b_off[chb + 2 * j];
                float hi = (i1 < 27) ? b_off[i1] : 0.0f;
                offa[j] = pack2(lo, hi);
            }
        }

        const float* wbase = g_wor + halfp * 16;
        for (int c = 0; c < CC; c++) {
            const float* xc = xb + c * CHS;
            float xq[5];
#pragma unroll
            for (int j = 0; j < 5; j++)
                xq[j] = p1v[j] ? __ldg(xc + p1o[j]) : 0.0f;
            float r0 = __shfl_xor_sync(0xffffffffu, halfp ? xq[1] : xq[0], 16);
            float r1 = __shfl_xor_sync(0xffffffffu, halfp ? xq[2] : xq[1], 16);
            float r2 = __shfl_xor_sync(0xffffffffu, halfp ? xq[3] : xq[2], 16);
            float r3 = __shfl_xor_sync(0xffffffffu, halfp ? xq[4] : xq[3], 16);
            ull X[9];
            X[0] = pack2(xq[0], xq[0]); X[1] = pack2(xq[1], xq[1]);
            X[2] = pack2(xq[2], xq[2]); X[3] = pack2(xq[3], xq[3]);
            X[4] = pack2(xq[4], xq[4]);
            X[5] = pack2(r0, r0); X[6] = pack2(r1, r1);
            X[7] = pack2(r2, r2); X[8] = pack2(r3, r3);

            const float* crow = wbase + c * 288;
#pragma unroll
            for (int i = 0; i < 9; i++) {
                const float* wp2 = crow + kord[i] * 32;
                ulonglong2 q0 = __ldg((const ulonglong2*)wp2);
                ulonglong2 q1 = __ldg((const ulonglong2*)wp2 + 1);
                ulonglong2 q2 = __ldg((const ulonglong2*)wp2 + 2);
                ull        q6 = __ldg((const ull*)wp2 + 6);
                offa[0] = ffma2(q0.x, X[i], offa[0]);
                offa[1] = ffma2(q0.y, X[i], offa[1]);
                offa[2] = ffma2(q1.x, X[i], offa[2]);
                offa[3] = ffma2(q1.y, X[i], offa[3]);
                offa[4] = ffma2(q2.x, X[i], offa[4]);
                offa[5] = ffma2(q2.y, X[i], offa[5]);
                offa[6] = ffma2(q6,   X[i], offa[6]);
            }
        }

        __syncthreads();   // BN staged; exsh region free to write
        {
            float l[14];
#pragma unroll
            for (int j = 0; j < 7; j++) unpack2(offa[j], l[2 * j], l[2 * j + 1]);
            int chb = halfp * 14;
#pragma unroll
            for (int j = 0; j < 14; j++)
                exsh[(chb + j) * 132 + p] = l[j];
        }
        __syncthreads();   // exsh ready
    }

    // =======================================================================
    // Role split. Ring: 2 slots x 4 channels. full ids 1,2; empty ids 3,4.
    // =======================================================================
    if (tid < 128) {
        // ----------------------- SAMPLER (producer) -----------------------
        const int spx = tid;      // pixel in row
        const int w   = spx;

        int   ofs0[9], stp[9];
        float cf[9][4];
#pragma unroll
        for (int k = 0; k < 9; k++) {
            float oy = exsh[(2 * k) * 132 + spx];
            float ox = exsh[(2 * k + 1) * 132 + spx];
            float m  = 1.0f / (1.0f + __expf(-exsh[(18 + k) * 132 + spx]));
            float py = (float)(h + k / 3 - 1) + oy;
            float px = (float)(w + k % 3 - 1) + ox;
            float y0f = floorf(py), x0f = floorf(px);
            float dy = py - y0f, dx = px - x0f;
            int y0 = (int)y0f, x0 = (int)x0f;
            int y1 = y0 + 1,   x1 = x0 + 1;
            bool vy0 = (y0 >= 0) & (y0 < HH), vy1 = (y1 >= 0) & (y1 < HH);
            bool vx0 = (x0 >= 0) & (x0 < WW), vx1 = (x1 >= 0) & (x1 < WW);
            int cy0 = min(max(y0, 0), HH - 1), cy1 = min(max(y1, 0), HH - 1);
            int cx0 = min(max(x0, 0), WW - 1), cx1 = min(max(x1, 0), WW - 1);
            ofs0[k] = cy0 * WW + cx0;
            stp[k]  = (((cy1 - cy0) * WW) << 16) | (cx1 - cx0);
            cf[k][0] = (vy0 && vx0) ? (1.0f - dy) * (1.0f - dx) * m : 0.0f;
            cf[k][1] = (vy0 && vx1) ? (1.0f - dy) * dx * m          : 0.0f;
            cf[k][2] = (vy1 && vx0) ? dy * (1.0f - dx) * m          : 0.0f;
            cf[k][3] = (vy1 && vx1) ? dy * dx * m                   : 0.0f;
        }
        __syncthreads();   // (A) exsh free -> vsh

        for (int cc = 0; cc < CC; cc += 4) {
            const int slot = (cc >> 2) & 1;
            if (cc >= 8) BAR_SYNC(3 + slot);             // wait empty

            const ull* xc = x4b + (cc >> 2) * CHS;       // this c4 plane
            float v0[9], v1[9], v2[9], v3[9];
#pragma unroll
            for (int k = 0; k < 9; k++) {
                int o0 = ofs0[k];
                int sx = stp[k] & 0xffff;
                int sy = stp[k] >> 16;
                ull q00 = __ldg(xc + o0);
                ull q01 = __ldg(xc + o0 + sx);
                ull q10 = __ldg(xc + o0 + sy);
                ull q11 = __ldg(xc + o0 + sy + sx);
                __half2 a00 = *reinterpret_cast<__half2*>(&q00);
                __half2 b00 = *(reinterpret_cast<__half2*>(&q00) + 1);
                __half2 a01 = *reinterpret_cast<__half2*>(&q01);
                __half2 b01 = *(reinterpret_cast<__half2*>(&q01) + 1);
                __half2 a10 = *reinterpret_cast<__half2*>(&q10);
                __half2 b10 = *(reinterpret_cast<__half2*>(&q10) + 1);
                __half2 a11 = *reinterpret_cast<__half2*>(&q11);
                __half2 b11 = *(reinterpret_cast<__half2*>(&q11) + 1);
                float2 f00a = __half22float2(a00), f00b = __half22float2(b00);
                float2 f01a = __half22float2(a01), f01b = __half22float2(b01);
                float2 f10a = __half22float2(a10), f10b = __half22float2(b10);
                float2 f11a = __half22float2(a11), f11b = __half22float2(b11);
                float c0 = cf[k][0], c1 = cf[k][1], c2 = cf[k][2], c3 = cf[k][3];
                v0[k] = c0 * f00a.x + c1 * f01a.x + c2 * f10a.x + c3 * f11a.x;
                v1[k] = c0 * f00a.y + c1 * f01a.y + c2 * f10a.y + c3 * f11a.y;
                v2[k] = c0 * f00b.x + c1 * f01b.x + c2 * f10b.x + c3 * f11b.x;
                v3[k] = c0 * f00b.y + c1 * f01b.y + c2 * f10b.y + c3 * f11b.y;
            }
            float* vb = vsh + slot * 4608 + spx;
#pragma unroll
            for (int k = 0; k < 9; k++) vb[k * 128] = v0[k];
#pragma unroll
            for (int k = 0; k < 9; k++) vb[1152 + k * 128] = v1[k];
#pragma unroll
            for (int k = 0; k < 9; k++) vb[2304 + k * 128] = v2[k];
#pragma unroll
            for (int k = 0; k < 9; k++) vb[3456 + k * 128] = v3[k];

            PBAR_SYNC();            // producer-only: drains producers' STS
            BAR_ARRIVE(1 + slot);   // signal full
        }
    } else {
        // ----------------------- CONSUMER ---------------------------------
        const int ctid = tid - 128;
        const int og   = ctid & 7;     // 8 outputs: o = og*8 .. og*8+7
        const int pxg  = ctid >> 3;    // 16 groups x 8 px
        const int og4  = og * 4;

        __syncthreads();   // (A)

        ull acc[32];
#pragma unroll
        for (int j = 0; j < 32; j++) acc[j] = 0ULL;

        for (int cc = 0; cc < CC; cc += 4) {
            const int slot = (cc >> 2) & 1;
            BAR_SYNC(1 + slot);                          // wait full
#pragma unroll
            for (int ci = 0; ci < 4; ci++) {
                const float* wr = g_wr + (cc + ci) * (9 * 64);
                const float* vr = vsh + slot * 4608 + ci * 1152 + pxg * 8;
#pragma unroll
                for (int k = 0; k < 9; k++) {
                    const float* wrk = wr + k * 64;
                    ulonglong2 wA = __ldg((const ulonglong2*)(wrk + og4));
                    ulonglong2 wB = __ldg((const ulonglong2*)(wrk + 32 + og4));
                    const float* vrk = vr + k * 128;
                    float4 a  = *(const float4*)(vrk);
                    float4 bq = *(const float4*)(vrk + 4);
                    ull vv0 = pack2(a.x, a.x),   vv1 = pack2(a.y, a.y);
                    ull vv2 = pack2(a.z, a.z),   vv3 = pack2(a.w, a.w);
                    ull vv4 = pack2(bq.x, bq.x), vv5 = pack2(bq.y, bq.y);
                    ull vv6 = pack2(bq.z, bq.z), vv7 = pack2(bq.w, bq.w);
                    acc[0]  = ffma2(wA.x, vv0, acc[0]);
                    acc[1]  = ffma2(wA.x, vv1, acc[1]);
                    acc[2]  = ffma2(wA.x, vv2, acc[2]);
                    acc[3]  = ffma2(wA.x, vv3, acc[3]);
                    acc[4]  = ffma2(wA.x, vv4, acc[4]);
                    acc[5]  = ffma2(wA.x, vv5, acc[5]);
                    acc[6]  = ffma2(wA.x, vv6, acc[6]);
                    acc[7]  = ffma2(wA.x, vv7, acc[7]);
                    acc[8]  = ffma2(wA.y, vv0, acc[8]);
                    acc[9]  = ffma2(wA.y, vv1, acc[9]);
                    acc[10] = ffma2(wA.y, vv2, acc[10]);
                    acc[11] = ffma2(wA.y, vv3, acc[11]);
                    acc[12] = ffma2(wA.y, vv4, acc[12]);
                    acc[13] = ffma2(wA.y, vv5, acc[13]);
                    acc[14] = ffma2(wA.y, vv6, acc[14]);
                    acc[15] = ffma2(wA.y, vv7, acc[15]);
                    acc[16] = ffma2(wB.x, vv0, acc[16]);
                    acc[17] = ffma2(wB.x, vv1, acc[17]);
                    acc[18] = ffma2(wB.x, vv2, acc[18]);
                    acc[19] = ffma2(wB.x, vv3, acc[19]);
                    acc[20] = ffma2(wB.x, vv4, acc[20]);
                    acc[21] = ffma2(wB.x, vv5, acc[21]);
                    acc[22] = ffma2(wB.x, vv6, acc[22]);
                    acc[23] = ffma2(wB.x, vv7, acc[23]);
                    acc[24] = ffma2(wB.y, vv0, acc[24]);
                    acc[25] = ffma2(wB.y, vv1, acc[25]);
                    acc[26] = ffma2(wB.y, vv2, acc[26]);
                    acc[27] = ffma2(wB.y, vv3, acc[27]);
                    acc[28] = ffma2(wB.y, vv4, acc[28]);
                    acc[29] = ffma2(wB.y, vv5, acc[29]);
                    acc[30] = ffma2(wB.y, vv6, acc[30]);
                    acc[31] = ffma2(wB.y, vv7, acc[31]);
                }
            }
            BAR_ARRIVE(3 + slot);                        // signal empty
        }

        // ---- BN + ReLU + store: 8 outputs x 8 px ----
        const int ew = pxg * 8;
        float* opb = out + (size_t)b * OO * CHS + h * WW + ew;
#pragma unroll
        for (int oi2 = 0; oi2 < 4; oi2++) {
            int o0 = og * 8 + 2 * oi2;
            float s0 = bscale[o0],     f0 = bshift[o0];
            float s1 = bscale[o0 + 1], f1 = bshift[o0 + 1];
            float lo[8], hi[8];
#pragma unroll
            for (int pj = 0; pj < 8; pj++)
                unpack2(acc[oi2 * 8 + pj], lo[pj], hi[pj]);
            float4 q0 = { fmaxf(lo[0] * s0 + f0, 0.0f), fmaxf(lo[1] * s0 + f0, 0.0f),
                          fmaxf(lo[2] * s0 + f0, 0.0f), fmaxf(lo[3] * s0 + f0, 0.0f) };
            float4 q1 = { fmaxf(lo[4] * s0 + f0, 0.0f), fmaxf(lo[5] * s0 + f0, 0.0f),
                          fmaxf(lo[6] * s0 + f0, 0.0f), fmaxf(lo[7] * s0 + f0, 0.0f) };
            float4 r0 = { fmaxf(hi[0] * s1 + f1, 0.0f), fmaxf(hi[1] * s1 + f1, 0.0f),
                          fmaxf(hi[2] * s1 + f1, 0.0f), fmaxf(hi[3] * s1 + f1, 0.0f) };
            float4 r1 = { fmaxf(hi[4] * s1 + f1, 0.0f), fmaxf(hi[5] * s1 + f1, 0.0f),
                          fmaxf(hi[6] * s1 + f1, 0.0f), fmaxf(hi[7] * s1 + f1, 0.0f) };
            *(float4*)(opb + (size_t)o0 * CHS)           = q0;
            *(float4*)(opb + (size_t)o0 * CHS + 4)       = q1;
            *(float4*)(opb + (size_t)(o0 + 1) * CHS)     = r0;
            *(float4*)(opb + (size_t)(o0 + 1) * CHS + 4) = r1;
        }
    }
}

// ---------------------------------------------------------------------------

extern "C" void kernel_launch(void* const* d_in, const int* in_sizes, int n_in,
                              void* d_out, int out_size)
{
    const float* x      = (const float*)d_in[0];
    const float* w_off  = (const float*)d_in[1];
    const float* b_off  = (const float*)d_in[2];
    const float* weight = (const float*)d_in[3];
    const float* bias   = (const float*)d_in[4];
    const float* gamma  = (const float*)d_in[5];
    const float* beta   = (const float*)d_in[6];
    const float* rmean  = (const float*)d_in[7];
    const float* rvar   = (const float*)d_in[8];
    float* out = (float*)d_out;

    const int smem = SMEM_FLOATS * sizeof(float);   // 37,376 B

    cudaFuncSetAttribute(dcn_2c_kernel,
                         cudaFuncAttributeMaxDynamicSharedMemorySize, smem);

    pack4_kernel<<<(BB * NC4 * CHS) / 256, 256>>>(x);
    reorder_kernel<<<(64 * 576 + 576 * 32 + 255) / 256, 256>>>(weight, w_off);
    dcn_2c_kernel<<<BB * HH, 256, smem>>>(
        x, b_off, bias, gamma, beta, rmean, rvar, out);
}

// round 16
// speedup vs baseline: 1.2385x; 1.2385x over previous
#include <cuda_runtime.h>
#include <cuda_fp16.h>
#include <cuda_bf16.h>
#include <math.h>

#define BB 4
#define CC 64
#define OO 64
#define HH 128
#define WW 128
#define CHS (HH * WW)
#define NC4 (CC / 4)

#define WPAD 68                    // main weight row floats (272B)

// SMEM float offsets
#define WSH_F 0
#define UNI_F (576 * WPAD)         // 39168: union {wosh 18432 | exsh 7280 | vsh 18432}
#define BN_F  (UNI_F + 18432)      // 57600
#define SMEM_FLOATS (BN_F + 128)   // 57728 floats = 230,912 B

typedef unsigned long long ull;

// channel-packed fp16 image: g_x4[b][c4][y][x] = 4 halves (ch 4c4..4c4+3)
__device__ ull g_x4[(size_t)BB * NC4 * CHS];

__device__ __forceinline__ ull pack2(float lo, float hi) {
    ull r; asm("mov.b64 %0, {%1, %2};" : "=l"(r) : "f"(lo), "f"(hi)); return r;
}
__device__ __forceinline__ void unpack2(ull v, float& lo, float& hi) {
    asm("mov.b64 {%0, %1}, %2;" : "=f"(lo), "=f"(hi) : "l"(v));
}
__device__ __forceinline__ ull ffma2(ull a, ull b, ull c) {
    ull d; asm("fma.rn.f32x2 %0, %1, %2, %3;" : "=l"(d) : "l"(a), "l"(b), "l"(c)); return d;
}

#define BAR_SYNC(id)   asm volatile("bar.sync %0, 512;"   :: "r"(id) : "memory")
#define BAR_ARRIVE(id) asm volatile("bar.arrive %0, 512;" :: "r"(id) : "memory")
#define PBAR_SYNC()    asm volatile("bar.sync 9, 256;" ::: "memory")

// ---------------------------------------------------------------------------
// Pre-pass: pack 4 channels per pixel into one ull of fp16.
// ---------------------------------------------------------------------------
__global__ void __launch_bounds__(256) pack4_kernel(const float* __restrict__ x)
{
    int i = blockIdx.x * 256 + threadIdx.x;          // 0 .. BB*NC4*CHS-1
    int pix = i & (CHS - 1);
    int c4  = (i >> 14) & (NC4 - 1);
    int b   = i >> 18;
    const float* xp = x + ((size_t)(b * CC + c4 * 4) << 14) + pix;
    __half2 lo = __floats2half2_rn(xp[0],       xp[CHS]);
    __half2 hi = __floats2half2_rn(xp[2 * CHS], xp[3 * CHS]);
    unsigned ulo = *reinterpret_cast<unsigned*>(&lo);
    unsigned uhi = *reinterpret_cast<unsigned*>(&hi);
    g_x4[i] = ((ull)uhi << 32) | ulo;
}

// ---------------------------------------------------------------------------
// Fused DCNv2 + BN + ReLU. CTA = 2 rows (256 px), 512 threads.
// Phase 1 (offset conv, fp32 x, software-pipelined x prefetch): all 16 warps.
// Phase 2: warps 0-7 = samplers (g_x4 corner LDG.64 gathers); warps 8-15 =
// consumers (FFMA2 GEMM tile). Ring: 2 slots x 4 channels.
// ---------------------------------------------------------------------------
__global__ void __launch_bounds__(512, 1) dcn_p4b_kernel(
    const float* __restrict__ x,
    const float* __restrict__ w_off,
    const float* __restrict__ b_off,
    const float* __restrict__ weight,
    const float* __restrict__ bias,
    const float* __restrict__ gamma,
    const float* __restrict__ beta,
    const float* __restrict__ rmean,
    const float* __restrict__ rvar,
    float* __restrict__ out)
{
    extern __shared__ float sm[];
    float* wsh    = sm + WSH_F;    // [576][WPAD], interleaved o-layout
    float* wosh   = sm + UNI_F;    // [576][32]   (phase 1)
    float* exsh   = sm + UNI_F;    // [28][260]   (offset exchange)
    float* vsh    = sm + UNI_F;    // [2 slots][4 ch][9][256] (phase 2 ring)
    float* bscale = sm + BN_F;
    float* bshift = bscale + 64;

    const int tid  = threadIdx.x;
    const int lane = tid & 31;
    const int w2   = tid >> 5;

    // ---- stage main weights with interleaved row layout ----
    for (int i = tid; i < OO * 576; i += 512) {
        int o = i / 576, ck = i % 576;
        int og = o >> 3, r = o & 7, ch = r >> 2, ri = r & 3;
        wsh[ck * WPAD + ch * 32 + og * 4 + ri] = weight[i];
    }
    for (int i = tid; i < 576 * 32; i += 512) wosh[i] = 0.0f;
    if (tid < 64) {
        int o = tid;
        float sc = gamma[o] * rsqrtf(rvar[o] + 1e-5f);
        bscale[o] = sc;
        bshift[o] = (bias[o] - rmean[o]) * sc + beta[o];
    }
    __syncthreads();
    for (int i = tid; i < 27 * 576; i += 512) {
        int oc = i / 576, ck = i % 576;
        int hf = (oc >= 14), j = oc - 14 * hf;
        wosh[ck * 32 + hf * 16 + j] = w_off[i];
    }
    __syncthreads();

    const int gr0 = blockIdx.x * 2;
    const int b   = gr0 >> 7;
    const float* xb = x + (size_t)b * CC * CHS;
    const ull* x4b  = g_x4 + (size_t)b * NC4 * CHS;

    // =======================================================================
    // Phase 1: offset conv, software-pipelined (prefetch x for c+1)
    // =======================================================================
    {
        const int p     = w2 * 16 + (lane & 15);
        const int halfp = lane >> 4;
        const int hp    = (gr0 + (p >> 7)) & 127;
        const int wp_   = p & 127;

        const int ty0[5] = {-1, -1, -1, 0, 0}, tx0[5] = {-1, 0, 1, -1, 0};
        const int ty1[5] = {0, 0, 1, 1, 1},    tx1[5] = {0, 1, -1, 0, 1};
        int p1o[5]; bool p1v[5];
#pragma unroll
        for (int j = 0; j < 5; j++) {
            int ty = halfp ? ty1[j] : ty0[j];
            int tx = halfp ? tx1[j] : tx0[j];
            int y = hp + ty, xx = wp_ + tx;
            p1v[j] = (y >= 0) & (y < HH) & (xx >= 0) & (xx < WW);
            p1o[j] = y * WW + xx;
        }
        int kord[9];
#pragma unroll
        for (int i = 0; i < 9; i++) kord[i] = halfp ? (4 + i) % 9 : i;

        ull offa[7];
        {
            int chb = halfp * 14;
#pragma unroll
            for (int j = 0; j < 7; j++) {
                int i1 = chb + 2 * j + 1;
                float lo = b_off[chb + 2 * j];
                float hi = (i1 < 27) ? b_off[i1] : 0.0f;
                offa[j] = pack2(lo, hi);
            }
        }

        const float* wbase = wosh + halfp * 16;

        // prologue: load channel 0
        float xq[5];
#pragma unroll
        for (int j = 0; j < 5; j++)
            xq[j] = p1v[j] ? __ldg(xb + p1o[j]) : 0.0f;

        for (int c = 0; c < CC; c++) {
            // prefetch channel c+1 (issued before the FFMA2 block)
            float xn[5];
            if (c < CC - 1) {
                const float* xnc = xb + (c + 1) * CHS;
#pragma unroll
                for (int j = 0; j < 5; j++)
                    xn[j] = p1v[j] ? __ldg(xnc + p1o[j]) : 0.0f;
            } else {
#pragma unroll
                for (int j = 0; j < 5; j++) xn[j] = 0.0f;
            }

            float r0 = __shfl_xor_sync(0xffffffffu, halfp ? xq[1] : xq[0], 16);
            float r1 = __shfl_xor_sync(0xffffffffu, halfp ? xq[2] : xq[1], 16);
            float r2 = __shfl_xor_sync(0xffffffffu, halfp ? xq[3] : xq[2], 16);
            float r3 = __shfl_xor_sync(0xffffffffu, halfp ? xq[4] : xq[3], 16);
            ull X[9];
            X[0] = pack2(xq[0], xq[0]); X[1] = pack2(xq[1], xq[1]);
            X[2] = pack2(xq[2], xq[2]); X[3] = pack2(xq[3], xq[3]);
            X[4] = pack2(xq[4], xq[4]);
            X[5] = pack2(r0, r0); X[6] = pack2(r1, r1);
            X[7] = pack2(r2, r2); X[8] = pack2(r3, r3);

            const float* crow = wbase + c * 288;
#pragma unroll
            for (int i = 0; i < 9; i++) {
                const float* wp2 = crow + kord[i] * 32;
                ulonglong2 q0 = ((const ulonglong2*)wp2)[0];
                ulonglong2 q1 = ((const ulonglong2*)wp2)[1];
                ulonglong2 q2 = ((const ulonglong2*)wp2)[2];
                ull        q6 = ((const ull*)wp2)[6];
                offa[0] = ffma2(q0.x, X[i], offa[0]);
                offa[1] = ffma2(q0.y, X[i], offa[1]);
                offa[2] = ffma2(q1.x, X[i], offa[2]);
                offa[3] = ffma2(q1.y, X[i], offa[3]);
                offa[4] = ffma2(q2.x, X[i], offa[4]);
                offa[5] = ffma2(q2.y, X[i], offa[5]);
                offa[6] = ffma2(q6,   X[i], offa[6]);
            }
#pragma unroll
            for (int j = 0; j < 5; j++) xq[j] = xn[j];
        }

        __syncthreads();   // wosh reads done; exsh may overwrite
        {
            float l[14];
#pragma unroll
            for (int j = 0; j < 7; j++) unpack2(offa[j], l[2 * j], l[2 * j + 1]);
            int chb = halfp * 14;
#pragma unroll
            for (int j = 0; j < 14; j++)
                exsh[(chb + j) * 260 + p] = l[j];
        }
        __syncthreads();   // exsh ready
    }

    // =======================================================================
    // Role split. Ring: 2 slots x 4 channels. full ids 1,2; empty ids 3,4.
    // =======================================================================
    if (tid < 256) {
        // ----------------------- SAMPLER (producer) -----------------------
        const int spx = tid;
        const int h   = (gr0 + (spx >> 7)) & 127;
        const int w   = spx & 127;

        int   ofs0[9], stp[9];
        float cf[9][4];
#pragma unroll
        for (int k = 0; k < 9; k++) {
            float oy = exsh[(2 * k) * 260 + spx];
            float ox = exsh[(2 * k + 1) * 260 + spx];
            float m  = 1.0f / (1.0f + __expf(-exsh[(18 + k) * 260 + spx]));
            float py = (float)(h + k / 3 - 1) + oy;
            float px = (float)(w + k % 3 - 1) + ox;
            float y0f = floorf(py), x0f = floorf(px);
            float dy = py - y0f, dx = px - x0f;
            int y0 = (int)y0f, x0 = (int)x0f;
            int y1 = y0 + 1,   x1 = x0 + 1;
            bool vy0 = (y0 >= 0) & (y0 < HH), vy1 = (y1 >= 0) & (y1 < HH);
            bool vx0 = (x0 >= 0) & (x0 < WW), vx1 = (x1 >= 0) & (x1 < WW);
            int cy0 = min(max(y0, 0), HH - 1), cy1 = min(max(y1, 0), HH - 1);
            int cx0 = min(max(x0, 0), WW - 1), cx1 = min(max(x1, 0), WW - 1);
            ofs0[k] = cy0 * WW + cx0;
            stp[k]  = (((cy1 - cy0) * WW) << 16) | (cx1 - cx0);
            cf[k][0] = (vy0 && vx0) ? (1.0f - dy) * (1.0f - dx) * m : 0.0f;
            cf[k][1] = (vy0 && vx1) ? (1.0f - dy) * dx * m          : 0.0f;
            cf[k][2] = (vy1 && vx0) ? dy * (1.0f - dx) * m          : 0.0f;
            cf[k][3] = (vy1 && vx1) ? dy * dx * m                   : 0.0f;
        }
        __syncthreads();   // (A) exsh free -> vsh

        for (int cc = 0; cc < CC; cc += 4) {
            const int slot = (cc >> 2) & 1;
            if (cc >= 8) BAR_SYNC(3 + slot);             // wait empty

            const ull* xc = x4b + (cc >> 2) * CHS;       // this c4 plane
            float v0[9], v1[9], v2[9], v3[9];
#pragma unroll
            for (int k = 0; k < 9; k++) {
                int o0 = ofs0[k];
                int sx = stp[k] & 0xffff;
                int sy = stp[k] >> 16;
                ull q00 = __ldg(xc + o0);
                ull q01 = __ldg(xc + o0 + sx);
                ull q10 = __ldg(xc + o0 + sy);
                ull q11 = __ldg(xc + o0 + sy + sx);
                __half2 a00 = *reinterpret_cast<__half2*>(&q00);
                __half2 b00 = *(reinterpret_cast<__half2*>(&q00) + 1);
                __half2 a01 = *reinterpret_cast<__half2*>(&q01);
                __half2 b01 = *(reinterpret_cast<__half2*>(&q01) + 1);
                __half2 a10 = *reinterpret_cast<__half2*>(&q10);
                __half2 b10 = *(reinterpret_cast<__half2*>(&q10) + 1);
                __half2 a11 = *reinterpret_cast<__half2*>(&q11);
                __half2 b11 = *(reinterpret_cast<__half2*>(&q11) + 1);
                float2 f00a = __half22float2(a00), f00b = __half22float2(b00);
                float2 f01a = __half22float2(a01), f01b = __half22float2(b01);
                float2 f10a = __half22float2(a10), f10b = __half22float2(b10);
                float2 f11a = __half22float2(a11), f11b = __half22float2(b11);
                float c0 = cf[k][0], c1 = cf[k][1], c2 = cf[k][2], c3 = cf[k][3];
                v0[k] = c0 * f00a.x + c1 * f01a.x + c2 * f10a.x + c3 * f11a.x;
                v1[k] = c0 * f00a.y + c1 * f01a.y + c2 * f10a.y + c3 * f11a.y;
                v2[k] = c0 * f00b.x + c1 * f01b.x + c2 * f10b.x + c3 * f11b.x;
                v3[k] = c0 * f00b.y + c1 * f01b.y + c2 * f10b.y + c3 * f11b.y;
            }
            float* vb = vsh + slot * 9216 + spx;
#pragma unroll
            for (int k = 0; k < 9; k++) vb[k * 256] = v0[k];
#pragma unroll
            for (int k = 0; k < 9; k++) vb[2304 + k * 256] = v1[k];
#pragma unroll
            for (int k = 0; k < 9; k++) vb[4608 + k * 256] = v2[k];
#pragma unroll
            for (int k = 0; k < 9; k++) vb[6912 + k * 256] = v3[k];

            PBAR_SYNC();            // producer-only: drains all producers' STS
            BAR_ARRIVE(1 + slot);   // signal full
        }
    } else {
        // ----------------------- CONSUMER ---------------------------------
        const int ctid = tid - 256;
        const int og   = ctid & 7;     // 8 outputs: o = og*8 .. og*8+7
        const int pxg  = ctid >> 3;    // 8 px: px = pxg*8 .. pxg*8+7
        const int og4  = og * 4;

        __syncthreads();   // (A)

        ull acc[32];
#pragma unroll
        for (int j = 0; j < 32; j++) acc[j] = 0ULL;

        for (int cc = 0; cc < CC; cc += 4) {
            const int slot = (cc >> 2) & 1;
            BAR_SYNC(1 + slot);                          // wait full
#pragma unroll
            for (int ci = 0; ci < 4; ci++) {
                const float* wr = wsh + (cc + ci) * (9 * WPAD);
                const float* vr = vsh + slot * 9216 + ci * 2304 + pxg * 8;
#pragma unroll
                for (int k = 0; k < 9; k++) {
                    const float* wrk = wr + k * WPAD;
                    ulonglong2 wA = *(const ulonglong2*)(wrk + og4);
                    ulonglong2 wB = *(const ulonglong2*)(wrk + 32 + og4);
                    const float* vrk = vr + k * 256;
                    float4 a  = *(const float4*)(vrk);
                    float4 bq = *(const float4*)(vrk + 4);
                    ull vv0 = pack2(a.x, a.x),   vv1 = pack2(a.y, a.y);
                    ull vv2 = pack2(a.z, a.z),   vv3 = pack2(a.w, a.w);
                    ull vv4 = pack2(bq.x, bq.x), vv5 = pack2(bq.y, bq.y);
                    ull vv6 = pack2(bq.z, bq.z), vv7 = pack2(bq.w, bq.w);
                    acc[0]  = ffma2(wA.x, vv0, acc[0]);
                    acc[1]  = ffma2(wA.x, vv1, acc[1]);
                    acc[2]  = ffma2(wA.x, vv2, acc[2]);
                    acc[3]  = ffma2(wA.x, vv3, acc[3]);
                    acc[4]  = ffma2(wA.x, vv4, acc[4]);
                    acc[5]  = ffma2(wA.x, vv5, acc[5]);
                    acc[6]  = ffma2(wA.x, vv6, acc[6]);
                    acc[7]  = ffma2(wA.x, vv7, acc[7]);
                    acc[8]  = ffma2(wA.y, vv0, acc[8]);
                    acc[9]  = ffma2(wA.y, vv1, acc[9]);
                    acc[10] = ffma2(wA.y, vv2, acc[10]);
                    acc[11] = ffma2(wA.y, vv3, acc[11]);
                    acc[12] = ffma2(wA.y, vv4, acc[12]);
                    acc[13] = ffma2(wA.y, vv5, acc[13]);
                    acc[14] = ffma2(wA.y, vv6, acc[14]);
                    acc[15] = ffma2(wA.y, vv7, acc[15]);
                    acc[16] = ffma2(wB.x, vv0, acc[16]);
                    acc[17] = ffma2(wB.x, vv1, acc[17]);
                    acc[18] = ffma2(wB.x, vv2, acc[18]);
                    acc[19] = ffma2(wB.x, vv3, acc[19]);
                    acc[20] = ffma2(wB.x, vv4, acc[20]);
                    acc[21] = ffma2(wB.x, vv5, acc[21]);
                    acc[22] = ffma2(wB.x, vv6, acc[22]);
                    acc[23] = ffma2(wB.x, vv7, acc[23]);
                    acc[24] = ffma2(wB.y, vv0, acc[24]);
                    acc[25] = ffma2(wB.y, vv1, acc[25]);
                    acc[26] = ffma2(wB.y, vv2, acc[26]);
                    acc[27] = ffma2(wB.y, vv3, acc[27]);
                    acc[28] = ffma2(wB.y, vv4, acc[28]);
                    acc[29] = ffma2(wB.y, vv5, acc[29]);
                    acc[30] = ffma2(wB.y, vv6, acc[30]);
                    acc[31] = ffma2(wB.y, vv7, acc[31]);
                }
            }
            BAR_ARRIVE(3 + slot);                        // signal empty
        }

        // ---- BN + ReLU + store: 8 outputs x 8 px ----
        const int px0 = pxg * 8;
        const int eh  = (gr0 + (px0 >> 7)) & 127;
        const int ew  = px0 & 127;
        float* opb = out + (size_t)b * OO * CHS + eh * WW + ew;
#pragma unroll
        for (int oi2 = 0; oi2 < 4; oi2++) {
            int o0 = og * 8 + 2 * oi2;
            float s0 = bscale[o0],     f0 = bshift[o0];
            float s1 = bscale[o0 + 1], f1 = bshift[o0 + 1];
            float lo[8], hi[8];
#pragma unroll
            for (int pj = 0; pj < 8; pj++)
                unpack2(acc[oi2 * 8 + pj], lo[pj], hi[pj]);
            float4 q0 = { fmaxf(lo[0] * s0 + f0, 0.0f), fmaxf(lo[1] * s0 + f0, 0.0f),
                          fmaxf(lo[2] * s0 + f0, 0.0f), fmaxf(lo[3] * s0 + f0, 0.0f) };
            float4 q1 = { fmaxf(lo[4] * s0 + f0, 0.0f), fmaxf(lo[5] * s0 + f0, 0.0f),
                          fmaxf(lo[6] * s0 + f0, 0.0f), fmaxf(lo[7] * s0 + f0, 0.0f) };
            float4 r0 = { fmaxf(hi[0] * s1 + f1, 0.0f), fmaxf(hi[1] * s1 + f1, 0.0f),
                          fmaxf(hi[2] * s1 + f1, 0.0f), fmaxf(hi[3] * s1 + f1, 0.0f) };
            float4 r1 = { fmaxf(hi[4] * s1 + f1, 0.0f), fmaxf(hi[5] * s1 + f1, 0.0f),
                          fmaxf(hi[6] * s1 + f1, 0.0f), fmaxf(hi[7] * s1 + f1, 0.0f) };
            *(float4*)(opb + (size_t)o0 * CHS)           = q0;
            *(float4*)(opb + (size_t)o0 * CHS + 4)       = q1;
            *(float4*)(opb + (size_t)(o0 + 1) * CHS)     = r0;
            *(float4*)(opb + (size_t)(o0 + 1) * CHS + 4) = r1;
        }
    }
}

// ---------------------------------------------------------------------------

extern "C" void kernel_launch(void* const* d_in, const int* in_sizes, int n_in,
                              void* d_out, int out_size)
{
    const float* x      = (const float*)d_in[0];
    const float* w_off  = (const float*)d_in[1];
    const float* b_off  = (const float*)d_in[2];
    const float* weight = (const float*)d_in[3];
    const float* bias   = (const float*)d_in[4];
    const float* gamma  = (const float*)d_in[5];
    const float* beta   = (const float*)d_in[6];
    const float* rmean  = (const float*)d_in[7];
    const float* rvar   = (const float*)d_in[8];
    float* out = (float*)d_out;

    const int smem = SMEM_FLOATS * sizeof(float);   // 230,912 B

    cudaFuncSetAttribute(dcn_p4b_kernel,
                         cudaFuncAttributeMaxDynamicSharedMemorySize, smem);

    pack4_kernel<<<(BB * NC4 * CHS) / 256, 256>>>(x);
    dcn_p4b_kernel<<<BB * HH / 2, 512, smem>>>(
        x, w_off, b_off, weight, bias, gamma, beta, rmean, rvar, out);
}

// round 17
// speedup vs baseline: 1.2741x; 1.0288x over previous
#include <cuda_runtime.h>
#include <cuda_fp16.h>
#include <cuda_bf16.h>
#include <math.h>

#define BB 4
#define CC 64
#define OO 64
#define HH 128
#define WW 128
#define CHS (HH * WW)
#define NC4 (CC / 4)

#define WPAD 68                    // main weight row floats (272B)

// SMEM float offsets
#define WSH_F 0
#define UNI_F (576 * WPAD)         // 39168: union {wosh 18432 | exsh 7280 | vsh 18432}
#define BN_F  (UNI_F + 18432)      // 57600
#define SMEM_FLOATS (BN_F + 128)   // 57728 floats = 230,912 B

typedef unsigned long long ull;

// channel-packed fp16 image: g_x4[b][c4][y][x] = 4 halves (ch 4c4..4c4+3)
__device__ ull g_x4[(size_t)BB * NC4 * CHS];

__device__ __forceinline__ ull pack2(float lo, float hi) {
    ull r; asm("mov.b64 %0, {%1, %2};" : "=l"(r) : "f"(lo), "f"(hi)); return r;
}
__device__ __forceinline__ void unpack2(ull v, float& lo, float& hi) {
    asm("mov.b64 {%0, %1}, %2;" : "=f"(lo), "=f"(hi) : "l"(v));
}
__device__ __forceinline__ ull ffma2(ull a, ull b, ull c) {
    ull d; asm("fma.rn.f32x2 %0, %1, %2, %3;" : "=l"(d) : "l"(a), "l"(b), "l"(c)); return d;
}
// unpack a packed-4ch ull into 4 floats
__device__ __forceinline__ void unp4(ull q, float* f) {
    __half2 a = *reinterpret_cast<__half2*>(&q);
    __half2 b = *(reinterpret_cast<__half2*>(&q) + 1);
    float2 fa = __half22float2(a);
    float2 fb = __half22float2(b);
    f[0] = fa.x; f[1] = fa.y; f[2] = fb.x; f[3] = fb.y;
}

#define BAR_SYNC(id)   asm volatile("bar.sync %0, 512;"   :: "r"(id) : "memory")
#define BAR_ARRIVE(id) asm volatile("bar.arrive %0, 512;" :: "r"(id) : "memory")
#define PBAR_SYNC()    asm volatile("bar.sync 9, 256;" ::: "memory")

// ---------------------------------------------------------------------------
// Pre-pass: pack 4 channels per pixel into one ull of fp16.
// ---------------------------------------------------------------------------
__global__ void __launch_bounds__(256) pack4_kernel(const float* __restrict__ x)
{
    int i = blockIdx.x * 256 + threadIdx.x;          // 0 .. BB*NC4*CHS-1
    int pix = i & (CHS - 1);
    int c4  = (i >> 14) & (NC4 - 1);
    int b   = i >> 18;
    const float* xp = x + ((size_t)(b * CC + c4 * 4) << 14) + pix;
    __half2 lo = __floats2half2_rn(xp[0],       xp[CHS]);
    __half2 hi = __floats2half2_rn(xp[2 * CHS], xp[3 * CHS]);
    unsigned ulo = *reinterpret_cast<unsigned*>(&lo);
    unsigned uhi = *reinterpret_cast<unsigned*>(&hi);
    g_x4[i] = ((ull)uhi << 32) | ulo;
}

// ---------------------------------------------------------------------------
// Fused DCNv2 + BN + ReLU. CTA = 2 rows (256 px), 512 threads.
// Phase 1 (offset conv): packed-4ch gathers (5 LDG.64 per 4 channels),
// lane-pair tap split, software-pipelined. Phase 2: warps 0-7 = samplers
// (g_x4 corner LDG.64 gathers); warps 8-15 = consumers (FFMA2 GEMM tile).
// Ring: 2 slots x 4 channels.
// ---------------------------------------------------------------------------
__global__ void __launch_bounds__(512, 1) dcn_p4c_kernel(
    const float* __restrict__ x,
    const float* __restrict__ w_off,
    const float* __restrict__ b_off,
    const float* __restrict__ weight,
    const float* __restrict__ bias,
    const float* __restrict__ gamma,
    const float* __restrict__ beta,
    const float* __restrict__ rmean,
    const float* __restrict__ rvar,
    float* __restrict__ out)
{
    extern __shared__ float sm[];
    float* wsh    = sm + WSH_F;    // [576][WPAD], interleaved o-layout
    float* wosh   = sm + UNI_F;    // [576][32]   (phase 1)
    float* exsh   = sm + UNI_F;    // [28][260]   (offset exchange)
    float* vsh    = sm + UNI_F;    // [2 slots][4 ch][9][256] (phase 2 ring)
    float* bscale = sm + BN_F;
    float* bshift = bscale + 64;

    const int tid  = threadIdx.x;
    const int lane = tid & 31;
    const int w2   = tid >> 5;

    // ---- stage main weights with interleaved row layout ----
    for (int i = tid; i < OO * 576; i += 512) {
        int o = i / 576, ck = i % 576;
        int og = o >> 3, r = o & 7, ch = r >> 2, ri = r & 3;
        wsh[ck * WPAD + ch * 32 + og * 4 + ri] = weight[i];
    }
    for (int i = tid; i < 576 * 32; i += 512) wosh[i] = 0.0f;
    if (tid < 64) {
        int o = tid;
        float sc = gamma[o] * rsqrtf(rvar[o] + 1e-5f);
        bscale[o] = sc;
        bshift[o] = (bias[o] - rmean[o]) * sc + beta[o];
    }
    __syncthreads();
    for (int i = tid; i < 27 * 576; i += 512) {
        int oc = i / 576, ck = i % 576;
        int hf = (oc >= 14), j = oc - 14 * hf;
        wosh[ck * 32 + hf * 16 + j] = w_off[i];
    }
    __syncthreads();

    const int gr0 = blockIdx.x * 2;
    const int b   = gr0 >> 7;
    const ull* x4b = g_x4 + (size_t)b * NC4 * CHS;

    // =======================================================================
    // Phase 1: offset conv, packed-4ch gathers + pipelined prefetch
    // =======================================================================
    {
        const int p     = w2 * 16 + (lane & 15);
        const int halfp = lane >> 4;
        const int hp    = (gr0 + (p >> 7)) & 127;
        const int wp_   = p & 127;

        const int ty0[5] = {-1, -1, -1, 0, 0}, tx0[5] = {-1, 0, 1, -1, 0};
        const int ty1[5] = {0, 0, 1, 1, 1},    tx1[5] = {0, 1, -1, 0, 1};
        int p1o[5]; bool p1v[5];
#pragma unroll
        for (int j = 0; j < 5; j++) {
            int ty = halfp ? ty1[j] : ty0[j];
            int tx = halfp ? tx1[j] : tx0[j];
            int y = hp + ty, xx = wp_ + tx;
            p1v[j] = (y >= 0) & (y < HH) & (xx >= 0) & (xx < WW);
            p1o[j] = y * WW + xx;
        }
        int kord[9];
#pragma unroll
        for (int i = 0; i < 9; i++) kord[i] = halfp ? (4 + i) % 9 : i;

        ull offa[7];
        {
            int chb = halfp * 14;
#pragma unroll
            for (int j = 0; j < 7; j++) {
                int i1 = chb + 2 * j + 1;
                float lo = b_off[chb + 2 * j];
                float hi = (i1 < 27) ? b_off[i1] : 0.0f;
                offa[j] = pack2(lo, hi);
            }
        }

        const float* wbase = wosh + halfp * 16;

        // prologue: load c4 group 0 (4 channels per ull)
        ull xq[5];
#pragma unroll
        for (int j = 0; j < 5; j++)
            xq[j] = p1v[j] ? __ldg(x4b + p1o[j]) : 0ULL;

        for (int c4 = 0; c4 < NC4; c4++) {
            // prefetch next c4 group
            ull xn[5];
            if (c4 < NC4 - 1) {
                const ull* xnc = x4b + (c4 + 1) * CHS;
#pragma unroll
                for (int j = 0; j < 5; j++)
                    xn[j] = p1v[j] ? __ldg(xnc + p1o[j]) : 0ULL;
            } else {
#pragma unroll
                for (int j = 0; j < 5; j++) xn[j] = 0ULL;
            }

            // exchange cross-half taps (64-bit shuffles)
            ull r0 = __shfl_xor_sync(0xffffffffu, halfp ? xq[1] : xq[0], 16);
            ull r1 = __shfl_xor_sync(0xffffffffu, halfp ? xq[2] : xq[1], 16);
            ull r2 = __shfl_xor_sync(0xffffffffu, halfp ? xq[3] : xq[2], 16);
            ull r3 = __shfl_xor_sync(0xffffffffu, halfp ? xq[4] : xq[3], 16);

            // unpack: vt[tap][ci]
            float vt[9][4];
            unp4(xq[0], vt[0]); unp4(xq[1], vt[1]); unp4(xq[2], vt[2]);
            unp4(xq[3], vt[3]); unp4(xq[4], vt[4]);
            unp4(r0, vt[5]);    unp4(r1, vt[6]);
            unp4(r2, vt[7]);    unp4(r3, vt[8]);

#pragma unroll
            for (int ci = 0; ci < 4; ci++) {
                const int c = c4 * 4 + ci;
                const float* crow = wbase + c * 288;
#pragma unroll
                for (int i = 0; i < 9; i++) {
                    ull X = pack2(vt[i][ci], vt[i][ci]);
                    const float* wp2 = crow + kord[i] * 32;
                    ulonglong2 q0 = ((const ulonglong2*)wp2)[0];
                    ulonglong2 q1 = ((const ulonglong2*)wp2)[1];
                    ulonglong2 q2 = ((const ulonglong2*)wp2)[2];
                    ull        q6 = ((const ull*)wp2)[6];
                    offa[0] = ffma2(q0.x, X, offa[0]);
                    offa[1] = ffma2(q0.y, X, offa[1]);
                    offa[2] = ffma2(q1.x, X, offa[2]);
                    offa[3] = ffma2(q1.y, X, offa[3]);
                    offa[4] = ffma2(q2.x, X, offa[4]);
                    offa[5] = ffma2(q2.y, X, offa[5]);
                    offa[6] = ffma2(q6,   X, offa[6]);
                }
            }
#pragma unroll
            for (int j = 0; j < 5; j++) xq[j] = xn[j];
        }

        __syncthreads();   // wosh reads done; exsh may overwrite
        {
            float l[14];
#pragma unroll
            for (int j = 0; j < 7; j++) unpack2(offa[j], l[2 * j], l[2 * j + 1]);
            int chb = halfp * 14;
#pragma unroll
            for (int j = 0; j < 14; j++)
                exsh[(chb + j) * 260 + p] = l[j];
        }
        __syncthreads();   // exsh ready
    }

    // =======================================================================
    // Role split. Ring: 2 slots x 4 channels. full ids 1,2; empty ids 3,4.
    // =======================================================================
    if (tid < 256) {
        // ----------------------- SAMPLER (producer) -----------------------
        const int spx = tid;
        const int h   = (gr0 + (spx >> 7)) & 127;
        const int w   = spx & 127;

        int   ofs0[9], stp[9];
        float cf[9][4];
#pragma unroll
        for (int k = 0; k < 9; k++) {
            float oy = exsh[(2 * k) * 260 + spx];
            float ox = exsh[(2 * k + 1) * 260 + spx];
            float m  = 1.0f / (1.0f + __expf(-exsh[(18 + k) * 260 + spx]));
            float py = (float)(h + k / 3 - 1) + oy;
            float px = (float)(w + k % 3 - 1) + ox;
            float y0f = floorf(py), x0f = floorf(px);
            float dy = py - y0f, dx = px - x0f;
            int y0 = (int)y0f, x0 = (int)x0f;
            int y1 = y0 + 1,   x1 = x0 + 1;
            bool vy0 = (y0 >= 0) & (y0 < HH), vy1 = (y1 >= 0) & (y1 < HH);
            bool vx0 = (x0 >= 0) & (x0 < WW), vx1 = (x1 >= 0) & (x1 < WW);
            int cy0 = min(max(y0, 0), HH - 1), cy1 = min(max(y1, 0), HH - 1);
            int cx0 = min(max(x0, 0), WW - 1), cx1 = min(max(x1, 0), WW - 1);
            ofs0[k] = cy0 * WW + cx0;
            stp[k]  = (((cy1 - cy0) * WW) << 16) | (cx1 - cx0);
            cf[k][0] = (vy0 && vx0) ? (1.0f - dy) * (1.0f - dx) * m : 0.0f;
            cf[k][1] = (vy0 && vx1) ? (1.0f - dy) * dx * m          : 0.0f;
            cf[k][2] = (vy1 && vx0) ? dy * (1.0f - dx) * m          : 0.0f;
            cf[k][3] = (vy1 && vx1) ? dy * dx * m                   : 0.0f;
        }
        __syncthreads();   // (A) exsh free -> vsh

        for (int cc = 0; cc < CC; cc += 4) {
            const int slot = (cc >> 2) & 1;
            if (cc >= 8) BAR_SYNC(3 + slot);             // wait empty

            const ull* xc = x4b + (cc >> 2) * CHS;       // this c4 plane
            float v0[9], v1[9], v2[9], v3[9];
#pragma unroll
            for (int k = 0; k < 9; k++) {
                int o0 = ofs0[k];
                int sx = stp[k] & 0xffff;
                int sy = stp[k] >> 16;
                ull q00 = __ldg(xc + o0);
                ull q01 = __ldg(xc + o0 + sx);
                ull q10 = __ldg(xc + o0 + sy);
                ull q11 = __ldg(xc + o0 + sy + sx);
                float f00[4], f01[4], f10[4], f11[4];
                unp4(q00, f00); unp4(q01, f01);
                unp4(q10, f10); unp4(q11, f11);
                float c0 = cf[k][0], c1 = cf[k][1], c2 = cf[k][2], c3 = cf[k][3];
                v0[k] = c0 * f00[0] + c1 * f01[0] + c2 * f10[0] + c3 * f11[0];
                v1[k] = c0 * f00[1] + c1 * f01[1] + c2 * f10[1] + c3 * f11[1];
                v2[k] = c0 * f00[2] + c1 * f01[2] + c2 * f10[2] + c3 * f11[2];
                v3[k] = c0 * f00[3] + c1 * f01[3] + c2 * f10[3] + c3 * f11[3];
            }
            float* vb = vsh + slot * 9216 + spx;
#pragma unroll
            for (int k = 0; k < 9; k++) vb[k * 256] = v0[k];
#pragma unroll
            for (int k = 0; k < 9; k++) vb[2304 + k * 256] = v1[k];
#pragma unroll
            for (int k = 0; k < 9; k++) vb[4608 + k * 256] = v2[k];
#pragma unroll
            for (int k = 0; k < 9; k++) vb[6912 + k * 256] = v3[k];

            PBAR_SYNC();            // producer-only: drains all producers' STS
            BAR_ARRIVE(1 + slot);   // signal full
        }
    } else {
        // ----------------------- CONSUMER ---------------------------------
        const int ctid = tid - 256;
        const int og   = ctid & 7;     // 8 outputs: o = og*8 .. og*8+7
        const int pxg  = ctid >> 3;    // 8 px: px = pxg*8 .. pxg*8+7
        const int og4  = og * 4;

        __syncthreads();   // (A)

        ull acc[32];
#pragma unroll
        for (int j = 0; j < 32; j++) acc[j] = 0ULL;

        for (int cc = 0; cc < CC; cc += 4) {
            const int slot = (cc >> 2) & 1;
            BAR_SYNC(1 + slot);                          // wait full
#pragma unroll
            for (int ci = 0; ci < 4; ci++) {
                const float* wr = wsh + (cc + ci) * (9 * WPAD);
                const float* vr = vsh + slot * 9216 + ci * 2304 + pxg * 8;
#pragma unroll
                for (int k = 0; k < 9; k++) {
                    const float* wrk = wr + k * WPAD;
                    ulonglong2 wA = *(const ulonglong2*)(wrk + og4);
                    ulonglong2 wB = *(const ulonglong2*)(wrk + 32 + og4);
                    const float* vrk = vr + k * 256;
                    float4 a  = *(const float4*)(vrk);
                    float4 bq = *(const float4*)(vrk + 4);
                    ull vv0 = pack2(a.x, a.x),   vv1 = pack2(a.y, a.y);
                    ull vv2 = pack2(a.z, a.z),   vv3 = pack2(a.w, a.w);
                    ull vv4 = pack2(bq.x, bq.x), vv5 = pack2(bq.y, bq.y);
                    ull vv6 = pack2(bq.z, bq.z), vv7 = pack2(bq.w, bq.w);
                    acc[0]  = ffma2(wA.x, vv0, acc[0]);
                    acc[1]  = ffma2(wA.x, vv1, acc[1]);
                    acc[2]  = ffma2(wA.x, vv2, acc[2]);
                    acc[3]  = ffma2(wA.x, vv3, acc[3]);
                    acc[4]  = ffma2(wA.x, vv4, acc[4]);
                    acc[5]  = ffma2(wA.x, vv5, acc[5]);
                    acc[6]  = ffma2(wA.x, vv6, acc[6]);
                    acc[7]  = ffma2(wA.x, vv7, acc[7]);
                    acc[8]  = ffma2(wA.y, vv0, acc[8]);
                    acc[9]  = ffma2(wA.y, vv1, acc[9]);
                    acc[10] = ffma2(wA.y, vv2, acc[10]);
                    acc[11] = ffma2(wA.y, vv3, acc[11]);
                    acc[12] = ffma2(wA.y, vv4, acc[12]);
                    acc[13] = ffma2(wA.y, vv5, acc[13]);
                    acc[14] = ffma2(wA.y, vv6, acc[14]);
                    acc[15] = ffma2(wA.y, vv7, acc[15]);
                    acc[16] = ffma2(wB.x, vv0, acc[16]);
                    acc[17] = ffma2(wB.x, vv1, acc[17]);
                    acc[18] = ffma2(wB.x, vv2, acc[18]);
                    acc[19] = ffma2(wB.x, vv3, acc[19]);
                    acc[20] = ffma2(wB.x, vv4, acc[20]);
                    acc[21] = ffma2(wB.x, vv5, acc[21]);
                    acc[22] = ffma2(wB.x, vv6, acc[22]);
                    acc[23] = ffma2(wB.x, vv7, acc[23]);
                    acc[24] = ffma2(wB.y, vv0, acc[24]);
                    acc[25] = ffma2(wB.y, vv1, acc[25]);
                    acc[26] = ffma2(wB.y, vv2, acc[26]);
                    acc[27] = ffma2(wB.y, vv3, acc[27]);
                    acc[28] = ffma2(wB.y, vv4, acc[28]);
                    acc[29] = ffma2(wB.y, vv5, acc[29]);
                    acc[30] = ffma2(wB.y, vv6, acc[30]);
                    acc[31] = ffma2(wB.y, vv7, acc[31]);
                }
            }
            BAR_ARRIVE(3 + slot);                        // signal empty
        }

        // ---- BN + ReLU + store: 8 outputs x 8 px ----
        const int px0 = pxg * 8;
        const int eh  = (gr0 + (px0 >> 7)) & 127;
        const int ew  = px0 & 127;
        float* opb = out + (size_t)b * OO * CHS + eh * WW + ew;
#pragma unroll
        for (int oi2 = 0; oi2 < 4; oi2++) {
            int o0 = og * 8 + 2 * oi2;
            float s0 = bscale[o0],     f0 = bshift[o0];
            float s1 = bscale[o0 + 1], f1 = bshift[o0 + 1];
            float lo[8], hi[8];
#pragma unroll
            for (int pj = 0; pj < 8; pj++)
                unpack2(acc[oi2 * 8 + pj], lo[pj], hi[pj]);
            float4 q0 = { fmaxf(lo[0] * s0 + f0, 0.0f), fmaxf(lo[1] * s0 + f0, 0.0f),
                          fmaxf(lo[2] * s0 + f0, 0.0f), fmaxf(lo[3] * s0 + f0, 0.0f) };
            float4 q1 = { fmaxf(lo[4] * s0 + f0, 0.0f), fmaxf(lo[5] * s0 + f0, 0.0f),
                          fmaxf(lo[6] * s0 + f0, 0.0f), fmaxf(lo[7] * s0 + f0, 0.0f) };
            float4 r0 = { fmaxf(hi[0] * s1 + f1, 0.0f), fmaxf(hi[1] * s1 + f1, 0.0f),
                          fmaxf(hi[2] * s1 + f1, 0.0f), fmaxf(hi[3] * s1 + f1, 0.0f) };
            float4 r1 = { fmaxf(hi[4] * s1 + f1, 0.0f), fmaxf(hi[5] * s1 + f1, 0.0f),
                          fmaxf(hi[6] * s1 + f1, 0.0f), fmaxf(hi[7] * s1 + f1, 0.0f) };
            *(float4*)(opb + (size_t)o0 * CHS)           = q0;
            *(float4*)(opb + (size_t)o0 * CHS + 4)       = q1;
            *(float4*)(opb + (size_t)(o0 + 1) * CHS)     = r0;
            *(float4*)(opb + (size_t)(o0 + 1) * CHS + 4) = r1;
        }
    }
}

// ---------------------------------------------------------------------------

extern "C" void kernel_launch(void* const* d_in, const int* in_sizes, int n_in,
                              void* d_out, int out_size)
{
    const float* x      = (const float*)d_in[0];
    const float* w_off  = (const float*)d_in[1];
    const float* b_off  = (const float*)d_in[2];
    const float* weight = (const float*)d_in[3];
    const float* bias   = (const float*)d_in[4];
    const float* gamma  = (const float*)d_in[5];
    const float* beta   = (const float*)d_in[6];
    const float* rmean  = (const float*)d_in[7];
    const float* rvar   = (const float*)d_in[8];
    float* out = (float*)d_out;

    const int smem = SMEM_FLOATS * sizeof(float);   // 230,912 B

    cudaFuncSetAttribute(dcn_p4c_kernel,
                         cudaFuncAttributeMaxDynamicSharedMemorySize, smem);

    pack4_kernel<<<(BB * NC4 * CHS) / 256, 256>>>(x);
    dcn_p4c_kernel<<<BB * HH / 2, 512, smem>>>(
        x, w_off, b_off, weight, bias, gamma, beta, rmean, rvar, out);
}